// round 8
// baseline (speedup 1.0000x reference)
#include <cuda_runtime.h>

#define P   128
#define NT  256
#define PT  132   // pitch for sT / sD (skewed)
#define PL  130   // pitch for Lsh (makes 8-row stride hit distinct banks)

struct __align__(16) Smem {
  float sT[P][PT];    // Theta (orig), later Theta+Delta
  float sD[P][PT];    // Tc buffer, later Delta (symmetric, zero diag)
  float Lsh[P][PL];   // L_w (127x127, row 127 zeroed)
  float rowk[PT];     // sweep: row k broadcast (gapped)
  float ek[PT];       // sweep: indicator e_k (gapped)
  float tvec[PT];     // scan: t-hat (gapped)
  float dvec[PT];     // scan: d-hat (gapped)
  float gsh[PT];      // scan: W row c (gapped)
  float uvec[PT];     // scan: u = W t-hat (gapped, uvec[c] = u[c]-1)
  float redT[8];
  float redD[8];
  float ucvc[2];
  float diag[P];
};

// gapped index: halves offset by +4 floats -> warp halves hit different banks
__device__ __forceinline__ int VIDX(int x) { return x + ((x >> 6) << 2); }

__global__ void __launch_bounds__(NT, 1)
spod_kernel(const float* __restrict__ Theta,
            const float* __restrict__ Lw,
            float* __restrict__ Out)
{
  extern __shared__ __align__(16) float smraw[];
  Smem* sm = reinterpret_cast<Smem*>(smraw);

  const int tid = threadIdx.x;
  const int b   = blockIdx.x;
  const int i   = tid >> 1;      // row owned by this thread
  const int jh  = tid & 1;       // which 64-column half
  const int j0  = jh << 6;       // 0 or 64
  const int vb  = jh ? 68 : 0;   // VIDX(j0)

  const float* Tin = Theta + (size_t)b * (P * P);

  // ---------------- Phase A: load Theta, L_w ----------------
  for (int idx = tid; idx < P * P; idx += NT)
    sm->sT[idx >> 7][idx & 127] = Tin[idx];
  for (int idx = tid; idx < 127 * 127; idx += NT) {
    int r = idx / 127;
    sm->Lsh[r][idx - r * 127] = Lw[idx];
  }
  if (tid < PL) sm->Lsh[127][tid] = 0.0f;
  if (tid < PT) sm->ek[tid] = 0.0f;
  __syncthreads();

  // ---------------- Phase B0: Tc[m][c] = Theta[m + (m>=c)][c] into sD ----------------
  for (int idx = tid; idx < 127 * P; idx += NT) {
    int m = idx >> 7, c = idx & 127;
    sm->sD[m][c] = sm->sT[m + (m >= c)][c];
  }
  __syncthreads();

  // ---------------- Phase B1: Y = Lsh @ Tc  (127x127 @ 127x128) ----------------
  const int tj = tid >> 4, ti = tid & 15;
  const int jr = tj * 8, ic = ti * 8;
  float acc[8][8];
  #pragma unroll
  for (int r = 0; r < 8; ++r)
    #pragma unroll
    for (int q = 0; q < 8; ++q) acc[r][q] = 0.0f;

  for (int m = 0; m < 127; ++m) {
    float4 t0 = *(const float4*)&sm->sD[m][ic];
    float4 t1 = *(const float4*)&sm->sD[m][ic + 4];
    float la[8];
    #pragma unroll
    for (int r = 0; r < 8; ++r) la[r] = sm->Lsh[jr + r][m];
    #pragma unroll
    for (int r = 0; r < 8; ++r) {
      acc[r][0] = fmaf(la[r], t0.x, acc[r][0]);
      acc[r][1] = fmaf(la[r], t0.y, acc[r][1]);
      acc[r][2] = fmaf(la[r], t0.z, acc[r][2]);
      acc[r][3] = fmaf(la[r], t0.w, acc[r][3]);
      acc[r][4] = fmaf(la[r], t1.x, acc[r][4]);
      acc[r][5] = fmaf(la[r], t1.y, acc[r][5]);
      acc[r][6] = fmaf(la[r], t1.z, acc[r][6]);
      acc[r][7] = fmaf(la[r], t1.w, acc[r][7]);
    }
  }
  __syncthreads();

  // ---------------- Phase B2: Delta (symmetric) into sD ----------------
  // Delta[ii][j] (ii>j) = Y[j][ii] - Theta[j][ii]
  #pragma unroll
  for (int r = 0; r < 8; ++r) {
    int j = jr + r;
    #pragma unroll
    for (int q = 0; q < 8; ++q) {
      int ii = ic + q;
      if (j < ii) {
        float dvl = acc[r][q] - sm->sT[j][ii];
        sm->sD[ii][j] = dvl;
        sm->sD[j][ii] = dvl;
      }
    }
  }
  if (tid < P) sm->sD[tid][tid] = 0.0f;
  __syncthreads();

  // ---------------- Phase C: W = inv(Theta) via register sweep ----------------
  float W[64];
  #pragma unroll
  for (int t = 0; t < 16; ++t) {
    float4 v4 = *(const float4*)&sm->sT[i][j0 + 4 * t];
    W[4*t+0] = v4.x; W[4*t+1] = v4.y; W[4*t+2] = v4.z; W[4*t+3] = v4.w;
  }

  for (int k = 0; k < P; ++k) {
    if (i == k) {
      #pragma unroll
      for (int t = 0; t < 16; ++t)
        *(float4*)&sm->rowk[vb + 4 * t] =
            make_float4(W[4*t], W[4*t+1], W[4*t+2], W[4*t+3]);
    }
    if (tid == 0) {
      sm->ek[VIDX(k)] = 1.0f;
      if (k > 0) sm->ek[VIDX(k - 1)] = 0.0f;
    }
    __syncthreads();

    float d     = sm->rowk[VIDX(k)];
    float inv_d = 1.0f / d;
    float ri    = sm->rowk[VIDX(i)];
    float s, mm;
    if (i == k) { s = 1.0f - inv_d;  mm = (d + 1.0f) * inv_d; }
    else        { s = ri * inv_d;    mm = ri - s * (d + 1.0f); }

    #pragma unroll
    for (int t = 0; t < 16; ++t) {
      float4 rv = *(const float4*)&sm->rowk[vb + 4 * t];
      float4 ev = *(const float4*)&sm->ek[vb + 4 * t];
      W[4*t+0] = fmaf(-mm, ev.x, fmaf(-s, rv.x, W[4*t+0]));
      W[4*t+1] = fmaf(-mm, ev.y, fmaf(-s, rv.y, W[4*t+1]));
      W[4*t+2] = fmaf(-mm, ev.z, fmaf(-s, rv.z, W[4*t+2]));
      W[4*t+3] = fmaf(-mm, ev.w, fmaf(-s, rv.w, W[4*t+3]));
    }
    __syncthreads();
  }
  #pragma unroll
  for (int t = 0; t < 64; ++t) W[t] = -W[t];   // sweep gives -A^{-1}

  // ---------------- Phase D: Theta += Delta ----------------
  #pragma unroll
  for (int t = 0; t < 16; ++t) {
    float4 a4 = *(const float4*)&sm->sT[i][j0 + 4 * t];
    float4 d4 = *(const float4*)&sm->sD[i][j0 + 4 * t];
    a4.x += d4.x; a4.y += d4.y; a4.z += d4.z; a4.w += d4.w;
    *(float4*)&sm->sT[i][j0 + 4 * t] = a4;
  }
  __syncthreads();

  // ---------------- Phase E: sequential column scan ----------------
  for (int c = 0; c < P; ++c) {
    const int vc = VIDX(c);
    if (tid < P) {
      int vt = VIDX(tid);
      sm->tvec[vt] = (tid == c) ? 0.0f : sm->sT[tid][c];
      sm->dvec[vt] = (tid == c) ? 0.0f : sm->sD[tid][c];
    }
    if (i == c) {
      #pragma unroll
      for (int t = 0; t < 16; ++t)
        *(float4*)&sm->gsh[vb + 4 * t] =
            make_float4(W[4*t], W[4*t+1], W[4*t+2], W[4*t+3]);
    }
    __syncthreads();

    // u = W t-hat, v = W d-hat (half-row partials, 8 independent chains)
    float4 upa = make_float4(0.f, 0.f, 0.f, 0.f);
    float4 vpa = make_float4(0.f, 0.f, 0.f, 0.f);
    #pragma unroll
    for (int t = 0; t < 16; ++t) {
      float4 tv = *(const float4*)&sm->tvec[vb + 4 * t];
      float4 dv = *(const float4*)&sm->dvec[vb + 4 * t];
      upa.x = fmaf(W[4*t+0], tv.x, upa.x);
      upa.y = fmaf(W[4*t+1], tv.y, upa.y);
      upa.z = fmaf(W[4*t+2], tv.z, upa.z);
      upa.w = fmaf(W[4*t+3], tv.w, upa.w);
      vpa.x = fmaf(W[4*t+0], dv.x, vpa.x);
      vpa.y = fmaf(W[4*t+1], dv.y, vpa.y);
      vpa.z = fmaf(W[4*t+2], dv.z, vpa.z);
      vpa.w = fmaf(W[4*t+3], dv.w, vpa.w);
    }
    float up = (upa.x + upa.y) + (upa.z + upa.w);
    float vp = (vpa.x + vpa.y) + (vpa.z + vpa.w);

    // dot partials (pre-combine halves): sum over threads = t̂·u, d̂·v
    float ti_ = sm->tvec[VIDX(i)];
    float di_ = sm->dvec[VIDX(i)];
    float s1p = ti_ * up;
    float scp = di_ * vp;

    // combine halves (partner = tid^1, same warp)
    float uf = up + __shfl_xor_sync(0xffffffffu, up, 1);
    float vf = vp + __shfl_xor_sync(0xffffffffu, vp, 1);
    if (jh == 0) {
      if (i == c) {
        sm->ucvc[0] = uf;            // true u[c]
        sm->ucvc[1] = vf;            // true v[c]
        sm->uvec[vc] = uf - 1.0f;    // bakes q[c] = -1 into the generic update
      } else {
        sm->uvec[VIDX(i)] = uf;
      }
    }

    #pragma unroll
    for (int o = 16; o > 0; o >>= 1) {
      s1p += __shfl_xor_sync(0xffffffffu, s1p, o);
      scp += __shfl_xor_sync(0xffffffffu, scp, o);
    }
    if ((tid & 31) == 0) { sm->redT[tid >> 5] = s1p; sm->redD[tid >> 5] = scp; }
    __syncthreads();

    float dott = 0.f, dotd = 0.f;
    #pragma unroll
    for (int w8 = 0; w8 < 8; ++w8) { dott += sm->redT[w8]; dotd += sm->redD[w8]; }

    float uc   = sm->ucvc[0];
    float vcv  = sm->ucvc[1];
    float w22  = sm->gsh[vc];
    float iw22 = 1.0f / w22;
    float s1    = dott - uc * uc * iw22;     // t12' invT11 t12
    float schur = dotd - vcv * vcv * iw22;   // d12' invT11 d12
    float t22n  = sm->sT[c][c] + schur;
    float w22n  = 1.0f / (t22n - s1);
    float alpha = uc * iw22;

    float gi = sm->gsh[VIDX(i)];
    float ui = sm->uvec[VIDX(i)];            // for i==c this is uc-1 -> qi ~ -1
    float qi = ui - alpha * gi;
    float cq = w22n * qi;
    float e1 = fmaf(-cq, alpha, -gi * iw22); // cg - cq*alpha
    float e2 = cq;

    if (tid == 0) sm->diag[c] = t22n;

    // W += e1 * g^T + e2 * u^T (row-wise); exact at row/col c via uvec[c] trick
    #pragma unroll
    for (int t = 0; t < 16; ++t) {
      float4 gv = *(const float4*)&sm->gsh[vb + 4 * t];
      float4 uv = *(const float4*)&sm->uvec[vb + 4 * t];
      W[4*t+0] = fmaf(e2, uv.x, fmaf(e1, gv.x, W[4*t+0]));
      W[4*t+1] = fmaf(e2, uv.y, fmaf(e1, gv.y, W[4*t+1]));
      W[4*t+2] = fmaf(e2, uv.z, fmaf(e1, gv.z, W[4*t+2]));
      W[4*t+3] = fmaf(e2, uv.w, fmaf(e1, gv.w, W[4*t+3]));
    }
    __syncthreads();
  }

  // ---------------- Phase F: set diagonal, write out ----------------
  if (tid < P) sm->sT[tid][tid] = sm->diag[tid];
  __syncthreads();
  float* Ob = Out + (size_t)b * (P * P);
  for (int idx = tid; idx < P * P; idx += NT)
    Ob[idx] = sm->sT[idx >> 7][idx & 127];
}

extern "C" void kernel_launch(void* const* d_in, const int* in_sizes, int n_in,
                              void* d_out, int out_size)
{
  const float* Theta = (const float*)d_in[0];
  const float* Lw    = (const float*)d_in[1];
  if (n_in >= 2 && in_sizes[0] < in_sizes[1]) {  // defensive: Theta is the big one
    const float* t = Theta; Theta = Lw; Lw = t;
  }
  float* Out = (float*)d_out;

  int Bn = in_sizes[0] / (P * P);   // 128

  cudaFuncSetAttribute(spod_kernel,
                       cudaFuncAttributeMaxDynamicSharedMemorySize,
                       (int)sizeof(Smem));
  spod_kernel<<<Bn, NT, sizeof(Smem)>>>(Theta, Lw, Out);
}

// round 9
// speedup vs baseline: 1.0684x; 1.0684x over previous
#include <cuda_runtime.h>

#define P   128
#define NT  256
#define PT  132   // pitch for sT / sD (skewed)
#define PL  130   // pitch for Lsh

typedef unsigned long long u64;

struct __align__(16) Smem {
  float sT[P][PT];     // Theta (orig), later Theta+Delta (symmetric)
  float sD[P][PT];     // Tc buffer, later Delta (symmetric, zero diag)
  float Lsh[P][PL];    // L_w (127x127, row 127 zeroed)
  float rowk[2][PT];   // sweep: double-buffered modified pivot row rkm
  float tvec[PT];      // scan: t-hat (gapped)
  float dvec[PT];      // scan: d-hat (gapped)
  float gsh[2][PT];    // scan: W row c (double-buffered, gapped)
  float uvec[PT];      // scan: u = W t-hat (gapped, uvec[c] = u[c]-1)
  float diag[P];
  float redT[8];
  float redD[8];
  float ucvc[2];
};

// gapped index: halves offset by +4 floats -> warp halves hit different banks
__device__ __forceinline__ int VIDX(int x) { return x + ((x >> 6) << 2); }

__device__ __forceinline__ u64 pk2s(float x) {
  u64 r; asm("mov.b64 %0,{%1,%1};" : "=l"(r) : "f"(x)); return r;
}
__device__ __forceinline__ u64 pk2(float x, float y) {
  u64 r; asm("mov.b64 %0,{%1,%2};" : "=l"(r) : "f"(x), "f"(y)); return r;
}
__device__ __forceinline__ float2 up2(u64 a) {
  float2 f; asm("mov.b64 {%0,%1},%2;" : "=f"(f.x), "=f"(f.y) : "l"(a)); return f;
}
__device__ __forceinline__ u64 f2ma(u64 a, u64 b, u64 c) {
  u64 d; asm("fma.rn.f32x2 %0,%1,%2,%3;" : "=l"(d) : "l"(a), "l"(b), "l"(c));
  return d;
}

__global__ void __launch_bounds__(NT, 1)
spod_kernel(const float* __restrict__ Theta,
            const float* __restrict__ Lw,
            float* __restrict__ Out)
{
  extern __shared__ __align__(16) float smraw[];
  Smem* sm = reinterpret_cast<Smem*>(smraw);

  const int tid = threadIdx.x;
  const int b   = blockIdx.x;
  const int i   = tid >> 1;      // row owned by this thread
  const int jh  = tid & 1;       // which 64-column half
  const int j0  = jh << 6;       // 0 or 64
  const int vb  = jh ? 68 : 0;   // VIDX(j0)

  const float* Tin = Theta + (size_t)b * (P * P);

  // ---------------- Phase A: load Theta, L_w ----------------
  for (int idx = tid; idx < P * P; idx += NT)
    sm->sT[idx >> 7][idx & 127] = Tin[idx];
  for (int idx = tid; idx < 127 * 127; idx += NT) {
    int r = idx / 127;
    sm->Lsh[r][idx - r * 127] = Lw[idx];
  }
  if (tid < PL) sm->Lsh[127][tid] = 0.0f;
  __syncthreads();

  // ---------------- Phase B0: Tc[m][c] = Theta[m + (m>=c)][c] ----------------
  for (int idx = tid; idx < 127 * P; idx += NT) {
    int m = idx >> 7, c = idx & 127;
    sm->sD[m][c] = sm->sT[m + (m >= c)][c];
  }
  __syncthreads();

  // ---------------- Phase B1: Y = Lsh @ Tc (packed f32x2) ----------------
  const int tj = tid >> 4, ti = tid & 15;
  const int jr = tj * 8, ic = ti * 8;
  u64 acc2[8][4];
  #pragma unroll
  for (int r = 0; r < 8; ++r)
    #pragma unroll
    for (int q = 0; q < 4; ++q) acc2[r][q] = 0ULL;

  #pragma unroll 1
  for (int m = 0; m < 127; ++m) {
    ulonglong2 ta = *(const ulonglong2*)&sm->sD[m][ic];
    ulonglong2 tb = *(const ulonglong2*)&sm->sD[m][ic + 4];
    #pragma unroll
    for (int r = 0; r < 8; ++r) {
      u64 lr = pk2s(sm->Lsh[jr + r][m]);
      acc2[r][0] = f2ma(lr, ta.x, acc2[r][0]);
      acc2[r][1] = f2ma(lr, ta.y, acc2[r][1]);
      acc2[r][2] = f2ma(lr, tb.x, acc2[r][2]);
      acc2[r][3] = f2ma(lr, tb.y, acc2[r][3]);
    }
  }
  __syncthreads();

  // ---------------- Phase B2: Delta (symmetric) into sD ----------------
  #pragma unroll
  for (int r = 0; r < 8; ++r) {
    int j = jr + r;
    #pragma unroll
    for (int q = 0; q < 4; ++q) {
      float2 f = up2(acc2[r][q]);
      int i0 = ic + 2 * q, i1 = i0 + 1;
      if (j < i0) { float d0 = f.x - sm->sT[j][i0]; sm->sD[i0][j] = d0; sm->sD[j][i0] = d0; }
      if (j < i1) { float d1 = f.y - sm->sT[j][i1]; sm->sD[i1][j] = d1; sm->sD[j][i1] = d1; }
    }
  }
  if (tid < P) sm->sD[tid][tid] = 0.0f;
  __syncthreads();

  // ---------------- Phase C: W = inv(Theta) via packed register sweep ----------------
  u64 W2[32];
  #pragma unroll
  for (int t = 0; t < 16; ++t) {
    ulonglong2 v = *(const ulonglong2*)&sm->sT[i][j0 + 4 * t];
    W2[2 * t] = v.x; W2[2 * t + 1] = v.y;
  }

  #pragma unroll 1
  for (int k = 0; k < P; ++k) {
    const int buf = k & 1;
    if (i == k) {
      #pragma unroll
      for (int t = 0; t < 16; ++t) {
        ulonglong2 o; o.x = W2[2 * t]; o.y = W2[2 * t + 1];
        *(ulonglong2*)&sm->rowk[buf][vb + 4 * t] = o;
      }
      if ((k >> 6) == jh) {           // my half holds column k: rkm[k] = d - 1
        float raw = sm->rowk[buf][VIDX(k)];
        sm->rowk[buf][VIDX(k)] = raw - 1.0f;
      }
    }
    __syncthreads();

    float dm1  = sm->rowk[buf][VIDX(k)];
    float invd = 1.0f / (dm1 + 1.0f);
    float ri   = sm->rowk[buf][VIDX(i)];
    float s    = (i == k) ? (1.0f - invd) : (ri * invd);
    u64 ns = pk2s(-s);
    #pragma unroll
    for (int t = 0; t < 16; ++t) {
      ulonglong2 rv = *(const ulonglong2*)&sm->rowk[buf][vb + 4 * t];
      W2[2 * t]     = f2ma(ns, rv.x, W2[2 * t]);
      W2[2 * t + 1] = f2ma(ns, rv.y, W2[2 * t + 1]);
    }
  }

  // negate (sweep gives -A^{-1}), then fix the constant +2 pivot-diag error
  #pragma unroll
  for (int t = 0; t < 32; ++t) W2[t] ^= 0x8000000080000000ULL;
  if ((i >> 6) == jh) {
    int p = i - j0;
    #pragma unroll
    for (int t = 0; t < 32; ++t)
      if (t == (p >> 1)) {
        float2 f = up2(W2[t]);
        if (p & 1) f.y += 2.0f; else f.x += 2.0f;
        W2[t] = pk2(f.x, f.y);
      }
  }

  // ---------------- Phase D: Theta += Delta ----------------
  #pragma unroll
  for (int t = 0; t < 16; ++t) {
    float4 a4 = *(const float4*)&sm->sT[i][j0 + 4 * t];
    float4 d4 = *(const float4*)&sm->sD[i][j0 + 4 * t];
    a4.x += d4.x; a4.y += d4.y; a4.z += d4.z; a4.w += d4.w;
    *(float4*)&sm->sT[i][j0 + 4 * t] = a4;
  }
  __syncthreads();

  // ---------------- Phase E prologue: vectors for c=0 ----------------
  {
    int r5 = tid & 127;
    if (tid < 128) sm->tvec[VIDX(r5)] = (r5 == 0) ? 0.0f : sm->sT[0][r5];
    else           sm->dvec[VIDX(r5)] = (r5 == 0) ? 0.0f : sm->sD[0][r5];
    if (i == 0) {
      #pragma unroll
      for (int t = 0; t < 16; ++t) {
        ulonglong2 o; o.x = W2[2 * t]; o.y = W2[2 * t + 1];
        *(ulonglong2*)&sm->gsh[0][vb + 4 * t] = o;
      }
    }
  }
  __syncthreads();

  // ---------------- Phase E: sequential column scan ----------------
  #pragma unroll 1
  for (int c = 0; c < P; ++c) {
    const int cb = c & 1;
    const int vc = VIDX(c);

    // -- Phase 1: u = W t-hat, v = W d-hat (packed) --
    u64 ua[4] = {0, 0, 0, 0}, va[4] = {0, 0, 0, 0};
    #pragma unroll
    for (int t = 0; t < 16; ++t) {
      ulonglong2 tv = *(const ulonglong2*)&sm->tvec[vb + 4 * t];
      ulonglong2 dv = *(const ulonglong2*)&sm->dvec[vb + 4 * t];
      ua[(2 * t) & 3]     = f2ma(W2[2 * t],     tv.x, ua[(2 * t) & 3]);
      ua[(2 * t + 1) & 3] = f2ma(W2[2 * t + 1], tv.y, ua[(2 * t + 1) & 3]);
      va[(2 * t) & 3]     = f2ma(W2[2 * t],     dv.x, va[(2 * t) & 3]);
      va[(2 * t + 1) & 3] = f2ma(W2[2 * t + 1], dv.y, va[(2 * t + 1) & 3]);
    }
    float2 a0 = up2(ua[0]), a1 = up2(ua[1]), a2 = up2(ua[2]), a3 = up2(ua[3]);
    float up = ((a0.x + a0.y) + (a1.x + a1.y)) + ((a2.x + a2.y) + (a3.x + a3.y));
    float2 b0 = up2(va[0]), b1 = up2(va[1]), b2 = up2(va[2]), b3 = up2(va[3]);
    float vp = ((b0.x + b0.y) + (b1.x + b1.y)) + ((b2.x + b2.y) + (b3.x + b3.y));

    float ti_ = sm->tvec[VIDX(i)];
    float di_ = sm->dvec[VIDX(i)];
    float s1p = ti_ * up;
    float scp = di_ * vp;

    float uf = up + __shfl_xor_sync(0xffffffffu, up, 1);
    float vf = vp + __shfl_xor_sync(0xffffffffu, vp, 1);
    if (jh == 0) {
      if (i == c) {
        sm->ucvc[0] = uf; sm->ucvc[1] = vf;
        sm->uvec[vc] = uf - 1.0f;           // bakes q[c] = -1 into generic update
      } else {
        sm->uvec[VIDX(i)] = uf;
      }
    }
    #pragma unroll
    for (int o = 16; o > 0; o >>= 1) {
      s1p += __shfl_xor_sync(0xffffffffu, s1p, o);
      scp += __shfl_xor_sync(0xffffffffu, scp, o);
    }
    if ((tid & 31) == 0) { sm->redT[tid >> 5] = s1p; sm->redD[tid >> 5] = scp; }
    __syncthreads();

    // -- Phase 2: scalars + rank-2 W update + prefetch next vectors --
    float dott = 0.f, dotd = 0.f;
    #pragma unroll
    for (int w8 = 0; w8 < 8; ++w8) { dott += sm->redT[w8]; dotd += sm->redD[w8]; }

    float uc    = sm->ucvc[0];
    float vcv   = sm->ucvc[1];
    float w22   = sm->gsh[cb][vc];
    float iw22  = 1.0f / w22;
    float s1    = dott - uc * uc * iw22;
    float schur = dotd - vcv * vcv * iw22;
    float t22n  = sm->sT[c][c] + schur;
    float w22n  = 1.0f / (t22n - s1);
    float alpha = uc * iw22;

    float gi = sm->gsh[cb][VIDX(i)];
    float ui = sm->uvec[VIDX(i)];
    float qi = ui - alpha * gi;
    float cq = w22n * qi;
    float e1 = fmaf(-cq, alpha, -gi * iw22);
    u64 e1p = pk2s(e1), e2p = pk2s(cq);

    #pragma unroll
    for (int t = 0; t < 16; ++t) {
      ulonglong2 gv = *(const ulonglong2*)&sm->gsh[cb][vb + 4 * t];
      ulonglong2 uv = *(const ulonglong2*)&sm->uvec[vb + 4 * t];
      W2[2 * t]     = f2ma(e2p, uv.x, f2ma(e1p, gv.x, W2[2 * t]));
      W2[2 * t + 1] = f2ma(e2p, uv.y, f2ma(e1p, gv.y, W2[2 * t + 1]));
    }
    if (tid == 0) sm->diag[c] = t22n;

    int cn = c + 1;
    if (cn < P) {
      int r5 = tid & 127;
      if (tid < 128) sm->tvec[VIDX(r5)] = (r5 == cn) ? 0.0f : sm->sT[cn][r5];
      else           sm->dvec[VIDX(r5)] = (r5 == cn) ? 0.0f : sm->sD[cn][r5];
      if (i == cn) {
        #pragma unroll
        for (int t = 0; t < 16; ++t) {
          ulonglong2 o; o.x = W2[2 * t]; o.y = W2[2 * t + 1];
          *(ulonglong2*)&sm->gsh[cn & 1][vb + 4 * t] = o;
        }
      }
    }
    __syncthreads();
  }

  // ---------------- Phase F: set diagonal, write out ----------------
  if (tid < P) sm->sT[tid][tid] = sm->diag[tid];
  __syncthreads();
  float* Ob = Out + (size_t)b * (P * P);
  for (int idx = tid; idx < P * P; idx += NT)
    Ob[idx] = sm->sT[idx >> 7][idx & 127];
}

extern "C" void kernel_launch(void* const* d_in, const int* in_sizes, int n_in,
                              void* d_out, int out_size)
{
  const float* Theta = (const float*)d_in[0];
  const float* Lw    = (const float*)d_in[1];
  if (n_in >= 2 && in_sizes[0] < in_sizes[1]) {
    const float* t = Theta; Theta = Lw; Lw = t;
  }
  float* Out = (float*)d_out;

  int Bn = in_sizes[0] / (P * P);   // 128

  cudaFuncSetAttribute(spod_kernel,
                       cudaFuncAttributeMaxDynamicSharedMemorySize,
                       (int)sizeof(Smem));
  spod_kernel<<<Bn, NT, sizeof(Smem)>>>(Theta, Lw, Out);
}